// round 16
// baseline (speedup 1.0000x reference)
#include <cuda_runtime.h>

typedef unsigned long long u64;
typedef unsigned int u32;

#define NPG 50
#define EPG 400
#define NGRAPH 32768
#define NEDGE (NGRAPH*EPG)
#define WPC 8                 // warps per CTA in gcn
#define GPW 8                 // graphs per warp (512 CTAs — best measured)
#define T1 (WPC*32)
#define BN_EPS 1e-5f

#define FMA2(acc,a,b) asm("fma.rn.f32x2 %0,%1,%2,%0;" : "+l"(acc) : "l"(a), "l"(b))
#define ADD2(acc,a)   asm("add.rn.f32x2 %0,%1,%0;"    : "+l"(acc) : "l"(a))
__device__ __forceinline__ u64 packf2(float lo, float hi) {
    u64 r; asm("mov.b64 %0,{%1,%2};" : "=l"(r) : "r"(__float_as_uint(lo)), "r"(__float_as_uint(hi)));
    return r;
}
__device__ __forceinline__ float lo32(u64 v){ return __uint_as_float((unsigned)v); }
__device__ __forceinline__ float hi32(u64 v){ return __uint_as_float((unsigned)(v>>32)); }

// ---------------- device scratch (static; no allocation) ----------------
__device__ u64   g_GGc[NPG*16];    // interleaved (G, Gc) folded fc1 weights
__device__ float g_e1[16];
__device__ float g_sum1[16], g_ss1[16];
__device__ float g_sum2[32], g_ss2[32];
__device__ float g_a1[NGRAPH*16];  // 2 MB
__device__ float g_a2[NGRAPH*32];  // 4 MB

// ---------------- prep: fold W1k@W2k into fc1, zero accumulators ----------------
__global__ void prep_kernel(const float* __restrict__ W11, const float* __restrict__ b11,
                            const float* __restrict__ W21, const float* __restrict__ b21,
                            const float* __restrict__ W12, const float* __restrict__ b12,
                            const float* __restrict__ W22, const float* __restrict__ b22,
                            const float* __restrict__ W13, const float* __restrict__ b13,
                            const float* __restrict__ W23, const float* __restrict__ b23,
                            const float* __restrict__ fc1w, const float* __restrict__ fc1b)
{
    __shared__ float u[12], cv[12], dv[12];
    int tid = threadIdx.x;
    if (tid < 12) {
        int k = tid / 4, o = tid % 4;
        const float* W1 = (k==0) ? W11 : ((k==1) ? W12 : W13);
        const float* W2 = (k==0) ? W21 : ((k==1) ? W22 : W23);
        const float* b1 = (k==0) ? b11 : ((k==1) ? b12 : b13);
        const float* b2 = (k==0) ? b21 : ((k==1) ? b22 : b23);
        float uu = 0.f, cc = 0.f;
        #pragma unroll
        for (int m = 0; m < 4; ++m) { uu += W1[m]*W2[m*4+o]; cc += b1[m]*W2[m*4+o]; }
        u[tid] = uu; cv[tid] = cc; dv[tid] = b2[o];
    }
    __syncthreads();
    for (int i = tid; i < NPG*16; i += blockDim.x) {
        int j = i >> 4, o = i & 15;
        float gg = 0.f, gc = 0.f;
        #pragma unroll
        for (int f = 0; f < 12; ++f) {
            float w = fc1w[(j*12+f)*16 + o];
            gg += u[f]*w; gc += cv[f]*w;
        }
        g_GGc[i] = packf2(gg, gc);
    }
    if (tid < 16) {
        float e = fc1b[tid];
        for (int j = 0; j < NPG; ++j)
            #pragma unroll
            for (int f = 0; f < 12; ++f)
                e += dv[f]*fc1w[(j*12+f)*16 + tid];
        g_e1[tid] = e;
        g_sum1[tid] = 0.f; g_ss1[tid] = 0.f;
    }
    if (tid < 32) { g_sum2[tid] = 0.f; g_ss2[tid] = 0.f; }
}

// ---------------- main GCN kernel: warp-per-graph, u64 masks, interleaved sweeps ----------------
__global__ void __launch_bounds__(T1, 4) gcn_kernel(const float* __restrict__ x,
                                                    const int* __restrict__ ei)
{
    __shared__ u32  sMask[WPC][NPG*2];        // 64-bit row masks
    __shared__ float sAx[WPC][NPG];           // accumulate target (x-path / degree)
    __shared__ float sAr[WPC][NPG];           // accumulate target (ones-path)
    __shared__ u64  sWxd[WPC][NPG];           // packed (x*dinv, dinv)
    __shared__ float sW2[WPC][NPG];           // sweep-2 input
    __shared__ u64  sYR[WPC][NPG];            // packed (yv, rv)
    __shared__ unsigned short sDup[WPC][EPG]; // duplicate-edge list
    __shared__ int  sNdup[WPC];
    __shared__ u64  sGGc[NPG*16];             // interleaved fc1 weights
    __shared__ float se1[16];

    int tid = threadIdx.x, w = tid >> 5, lane = tid & 31;
    for (int i = tid; i < NPG*16; i += T1) sGGc[i] = g_GGc[i];
    if (tid < 16) se1[tid] = g_e1[tid];
    __syncthreads();

    u32*  mask = sMask[w];
    float* ax  = sAx[w];
    float* ar  = sAr[w];
    u64*  wxd  = sWxd[w];
    float* w2  = sW2[w];
    u64*  yr   = sYR[w];
    unsigned short* dup = sDup[w];

    const int r1 = lane, r2 = 32 + lane;
    const bool has2 = (lane < NPG - 32);
    float psum = 0.f, pss = 0.f;
    int gbase = (blockIdx.x * WPC + w) * GPW;

    for (int gi = 0; gi < GPW; ++gi) {
        int g = gbase + gi, nb = g*NPG, eb = g*EPG;
        // P0: zero ALL 100 mask words + load x
        float x1 = x[nb + r1];
        float x2 = has2 ? x[nb + r2] : 0.f;
        mask[lane] = 0; mask[32 + lane] = 0; mask[64 + lane] = 0;
        if (lane < 2*NPG - 96) mask[96 + lane] = 0;
        if (lane == 0) sNdup[w] = 0;
        __syncwarp();
        // P1: build bitmask adjacency; atomicOr detects duplicates
        #pragma unroll 4
        for (int e = lane; e < EPG; e += 32) {
            int s = ei[eb + e] - nb;
            int d = ei[NEDGE + eb + e] - nb;
            u32 bit = 1u << (s & 31);
            u32 old = atomicOr(&mask[d*2 + (s >> 5)], bit);
            if (old & bit) {
                int k = atomicAdd(&sNdup[w], 1);
                dup[k] = (unsigned short)(d*64 + s);
            }
        }
        __syncwarp();
        int nd = sNdup[w];
        // P2: u64 masks -> registers; degree = 1 + popcll (+ dup events)
        u64 ma = (u64)mask[2*r1] | ((u64)mask[2*r1+1] << 32);
        u64 mb = 0;
        if (has2) mb = (u64)mask[2*r2] | ((u64)mask[2*r2+1] << 32);
        ax[r1] = 1.f + (float)__popcll(ma);
        if (has2) ax[r2] = 1.f + (float)__popcll(mb);
        __syncwarp();
        for (int k = lane; k < nd; k += 32) atomicAdd(&ax[dup[k] >> 6], 1.0f);
        __syncwarp();
        float di1 = rsqrtf(ax[r1]), di2 = 0.f;
        u64 idA = packf2(x1*di1, di1), idB = 0;
        wxd[r1] = idA;
        if (has2) { di2 = rsqrtf(ax[r2]); idB = packf2(x2*di2, di2); wxd[r2] = idB; }
        __syncwarp();
        // P3: sweep 1 — both rows interleaved (2 independent LDS->ADD2 chains)
        {
            u64 A = idA, B = idB;
            u64 qa = ma, qb = mb;
            while (qa | qb) {
                if (qa) { int j = __ffsll(qa)-1; qa &= qa-1; u64 v = wxd[j]; ADD2(A, v); }
                if (qb) { int j = __ffsll(qb)-1; qb &= qb-1; u64 v = wxd[j]; ADD2(B, v); }
            }
            ax[r1] = lo32(A); ar[r1] = hi32(A);
            if (has2) { ax[r2] = lo32(B); ar[r2] = hi32(B); }
        }
        __syncwarp();
        for (int k = lane; k < nd; k += 32) {
            int c = dup[k]; u64 v = wxd[c & 63];
            atomicAdd(&ax[c >> 6], lo32(v));
            atomicAdd(&ar[c >> 6], hi32(v));
        }
        __syncwarp();
        float rv1 = ar[r1]*di1, rv2 = 0.f;
        float w2a = ax[r1]*di1*di1, w2b = 0.f;
        w2[r1] = w2a;
        if (has2) { rv2 = ar[r2]*di2; w2b = ax[r2]*di2*di2; w2[r2] = w2b; }
        __syncwarp();
        // P4: sweep 2 — scalar, both rows interleaved
        {
            float a = w2a, b = w2b;
            u64 qa = ma, qb = mb;
            while (qa | qb) {
                if (qa) { int j = __ffsll(qa)-1; qa &= qa-1; a += w2[j]; }
                if (qb) { int j = __ffsll(qb)-1; qb &= qb-1; b += w2[j]; }
            }
            ax[r1] = a;
            if (has2) ax[r2] = b;
        }
        __syncwarp();
        for (int k = lane; k < nd; k += 32) {
            int c = dup[k];
            atomicAdd(&ax[c >> 6], w2[c & 63]);
        }
        __syncwarp();
        yr[r1] = packf2(ax[r1]*di1, rv1);
        if (has2) yr[r2] = packf2(ax[r2]*di2, rv2);
        __syncwarp();
        // P5: fc1 — a1[g,o] = e1[o] + Σ_j yv[j]G[j,o] + rv[j]Gc[j,o]
        {
            int o = lane & 15, half = lane >> 4;
            int j0 = half * 25;
            u64 acc = 0;
            #pragma unroll
            for (int j = 0; j < 25; ++j) {
                u64 y = yr[j0 + j];
                u64 gg = sGGc[(j0 + j)*16 + o];
                FMA2(acc, y, gg);
            }
            float s = lo32(acc) + hi32(acc);
            s += __shfl_down_sync(0xffffffffu, s, 16);
            if (lane < 16) {
                float a = fmaxf(se1[o] + s, 0.f);
                g_a1[g*16 + o] = a;
                psum += a; pss += a*a;
            }
        }
        __syncwarp();
    }
    if (lane < 16) { atomicAdd(&g_sum1[lane], psum); atomicAdd(&g_ss1[lane], pss); }
}

// ---------------- fc2: 2 threads/graph — BN1 fold + GEMV + relu -> g_a2 + BN2 stats ----------------
__global__ void __launch_bounds__(128) fc2_kernel(const float* __restrict__ fc2w,
                                                  const float* __restrict__ fc2b,
                                                  const float* __restrict__ g1,
                                                  const float* __restrict__ bb1)
{
    __shared__ float sS[16], sOff[16];
    __shared__ float4 sW4[16*8];
    __shared__ float sc2[32];
    __shared__ float tile[4][16][33];
    __shared__ float rsum[32], rss[32];
    int tid = threadIdx.x, lane = tid & 31, w = tid >> 5;
    if (tid < 16) {
        float m = g_sum1[tid] * (1.0f/NGRAPH);
        float v = g_ss1[tid] * (1.0f/NGRAPH) - m*m;
        float sc = rsqrtf(v + BN_EPS) * g1[tid];
        sS[tid] = sc; sOff[tid] = bb1[tid] - m*sc;
    }
    if (tid < 32) { rsum[tid] = 0.f; rss[tid] = 0.f; }
    __syncthreads();
    float* sW = (float*)sW4;
    for (int i = tid; i < 512; i += 128) sW[i] = sS[i >> 5] * fc2w[i];
    if (tid < 32) {
        float c = fc2b[tid];
        #pragma unroll
        for (int r = 0; r < 16; ++r) c += sOff[r]*fc2w[r*32+tid];
        sc2[tid] = c;
    }
    __syncthreads();

    int gt = blockIdx.x*128 + tid;
    int b = gt >> 1, half = gt & 1;           // 2 threads per graph
    const float4* a4 = (const float4*)&g_a1[b*16];
    float4 r0 = a4[0], r1 = a4[1], r2 = a4[2], r3 = a4[3];
    float a[16] = {r0.x,r0.y,r0.z,r0.w, r1.x,r1.y,r1.z,r1.w,
                   r2.x,r2.y,r2.z,r2.w, r3.x,r3.y,r3.z,r3.w};
    float z[16];
    float4* out4 = (float4*)&g_a2[b*32 + half*16];
    #pragma unroll
    for (int q = 0; q < 4; ++q) {
        int o4 = half*4 + q;
        float4 acc = make_float4(sc2[o4*4], sc2[o4*4+1], sc2[o4*4+2], sc2[o4*4+3]);
        #pragma unroll
        for (int i = 0; i < 16; ++i) {
            float4 ww = sW4[i*8 + o4];
            acc.x += a[i]*ww.x; acc.y += a[i]*ww.y; acc.z += a[i]*ww.z; acc.w += a[i]*ww.w;
        }
        acc.x = fmaxf(acc.x, 0.f); acc.y = fmaxf(acc.y, 0.f);
        acc.z = fmaxf(acc.z, 0.f); acc.w = fmaxf(acc.w, 0.f);
        out4[q] = acc;
        z[q*4] = acc.x; z[q*4+1] = acc.y; z[q*4+2] = acc.z; z[q*4+3] = acc.w;
    }
    // BN2 stats: warp covers 16 graphs × 32 cols; tile[graph-in-warp][col]
    {
        float* trow = &tile[w][lane >> 1][(lane & 1)*16];
        #pragma unroll
        for (int i = 0; i < 16; ++i) trow[i] = z[i];
    }
    __syncwarp();
    float s = 0.f, ss = 0.f;
    #pragma unroll
    for (int j = 0; j < 16; ++j) {
        float v = tile[w][j][lane];
        s += v; ss += v*v;
    }
    atomicAdd(&rsum[lane], s);
    atomicAdd(&rss[lane], ss);
    __syncthreads();
    if (tid < 32) { atomicAdd(&g_sum2[tid], rsum[tid]); atomicAdd(&g_ss2[tid], rss[tid]); }
}

// ---------------- fc3: 2 threads/graph — BN2 fold + final logits ----------------
__global__ void __launch_bounds__(128) fc3_kernel(float* __restrict__ out,
                                                  const float* __restrict__ fc3w,
                                                  const float* __restrict__ fc3b,
                                                  const float* __restrict__ g2,
                                                  const float* __restrict__ bb2)
{
    __shared__ float sS[32], sOff[32], sW[64], sc3[2];
    int tid = threadIdx.x;
    if (tid < 32) {
        float m = g_sum2[tid] * (1.0f/NGRAPH);
        float v = g_ss2[tid] * (1.0f/NGRAPH) - m*m;
        float sc = rsqrtf(v + BN_EPS) * g2[tid];
        sS[tid] = sc; sOff[tid] = bb2[tid] - m*sc;
    }
    __syncthreads();
    if (tid < 64) sW[tid] = sS[tid >> 1] * fc3w[tid];
    if (tid < 2) {
        float c = fc3b[tid];
        #pragma unroll
        for (int r = 0; r < 32; ++r) c += sOff[r]*fc3w[r*2+tid];
        sc3[tid] = c;
    }
    __syncthreads();
    int gt = blockIdx.x*128 + tid;
    int b = gt >> 1, half = gt & 1;
    const float4* a2r = (const float4*)&g_a2[b*32 + half*16];
    float o0 = half ? 0.f : sc3[0];
    float o1 = half ? 0.f : sc3[1];
    #pragma unroll
    for (int q = 0; q < 4; ++q) {
        float4 v = a2r[q];
        int c0 = half*16 + q*4;
        o0 += v.x*sW[(c0+0)*2]   + v.y*sW[(c0+1)*2]   + v.z*sW[(c0+2)*2]   + v.w*sW[(c0+3)*2];
        o1 += v.x*sW[(c0+0)*2+1] + v.y*sW[(c0+1)*2+1] + v.z*sW[(c0+2)*2+1] + v.w*sW[(c0+3)*2+1];
    }
    o0 += __shfl_down_sync(0xffffffffu, o0, 1);
    o1 += __shfl_down_sync(0xffffffffu, o1, 1);
    if (half == 0) ((float2*)out)[b] = make_float2(o0, o1);
}

// ---------------- launch ----------------
extern "C" void kernel_launch(void* const* d_in, const int* in_sizes, int n_in,
                              void* d_out, int out_size)
{
    const float* x    = (const float*)d_in[0];
    const int*   ei   = (const int*)  d_in[1];
    const float* W11  = (const float*)d_in[2];
    const float* b11  = (const float*)d_in[3];
    const float* W21  = (const float*)d_in[4];
    const float* b21  = (const float*)d_in[5];
    const float* W12  = (const float*)d_in[6];
    const float* b12  = (const float*)d_in[7];
    const float* W22  = (const float*)d_in[8];
    const float* b22  = (const float*)d_in[9];
    const float* W13  = (const float*)d_in[10];
    const float* b13  = (const float*)d_in[11];
    const float* W23  = (const float*)d_in[12];
    const float* b23  = (const float*)d_in[13];
    const float* fc1w = (const float*)d_in[14];
    const float* fc1b = (const float*)d_in[15];
    const float* bn1g = (const float*)d_in[16];
    const float* bn1b = (const float*)d_in[17];
    const float* fc2w = (const float*)d_in[18];
    const float* fc2b = (const float*)d_in[19];
    const float* bn2g = (const float*)d_in[20];
    const float* bn2b = (const float*)d_in[21];
    const float* fc3w = (const float*)d_in[22];
    const float* fc3b = (const float*)d_in[23];

    prep_kernel<<<1, 256>>>(W11,b11,W21,b21,W12,b12,W22,b22,W13,b13,W23,b23,fc1w,fc1b);
    gcn_kernel<<<NGRAPH/(WPC*GPW), T1>>>(x, ei);
    fc2_kernel<<<NGRAPH*2/128, 128>>>(fc2w, fc2b, bn1g, bn1b);
    fc3_kernel<<<NGRAPH*2/128, 128>>>((float*)d_out, fc3w, fc3b, bn2g, bn2b);
}

// round 17
// speedup vs baseline: 1.2314x; 1.2314x over previous
#include <cuda_runtime.h>

typedef unsigned long long u64;
typedef unsigned int u32;

#define NPG 50
#define EPG 400
#define NGRAPH 32768
#define NEDGE (NGRAPH*EPG)
#define WPC 8                 // warps per CTA in gcn
#define GPW 8                 // graphs per warp (512 CTAs — best measured)
#define T1 (WPC*32)
#define BN_EPS 1e-5f

#define FMA2(acc,a,b) asm("fma.rn.f32x2 %0,%1,%2,%0;" : "+l"(acc) : "l"(a), "l"(b))
#define ADD2(acc,a)   asm("add.rn.f32x2 %0,%1,%0;"    : "+l"(acc) : "l"(a))
__device__ __forceinline__ u64 packf2(float lo, float hi) {
    u64 r; asm("mov.b64 %0,{%1,%2};" : "=l"(r) : "r"(__float_as_uint(lo)), "r"(__float_as_uint(hi)));
    return r;
}
__device__ __forceinline__ float lo32(u64 v){ return __uint_as_float((unsigned)v); }
__device__ __forceinline__ float hi32(u64 v){ return __uint_as_float((unsigned)(v>>32)); }

// ---------------- device scratch (static; no allocation) ----------------
__device__ u64   g_GGc[NPG*16];    // interleaved (G, Gc) folded fc1 weights
__device__ float g_e1[16];
__device__ float g_sum1[16], g_ss1[16];
__device__ float g_sum2[32], g_ss2[32];
__device__ float g_a1[NGRAPH*16];  // 2 MB
__device__ float g_a2[NGRAPH*32];  // 4 MB

// ---------------- prep: fold W1k@W2k into fc1, zero accumulators ----------------
__global__ void prep_kernel(const float* __restrict__ W11, const float* __restrict__ b11,
                            const float* __restrict__ W21, const float* __restrict__ b21,
                            const float* __restrict__ W12, const float* __restrict__ b12,
                            const float* __restrict__ W22, const float* __restrict__ b22,
                            const float* __restrict__ W13, const float* __restrict__ b13,
                            const float* __restrict__ W23, const float* __restrict__ b23,
                            const float* __restrict__ fc1w, const float* __restrict__ fc1b)
{
    __shared__ float u[12], cv[12], dv[12];
    int tid = threadIdx.x;
    if (tid < 12) {
        int k = tid / 4, o = tid % 4;
        const float* W1 = (k==0) ? W11 : ((k==1) ? W12 : W13);
        const float* W2 = (k==0) ? W21 : ((k==1) ? W22 : W23);
        const float* b1 = (k==0) ? b11 : ((k==1) ? b12 : b13);
        const float* b2 = (k==0) ? b21 : ((k==1) ? b22 : b23);
        float uu = 0.f, cc = 0.f;
        #pragma unroll
        for (int m = 0; m < 4; ++m) { uu += W1[m]*W2[m*4+o]; cc += b1[m]*W2[m*4+o]; }
        u[tid] = uu; cv[tid] = cc; dv[tid] = b2[o];
    }
    __syncthreads();
    for (int i = tid; i < NPG*16; i += blockDim.x) {
        int j = i >> 4, o = i & 15;
        float gg = 0.f, gc = 0.f;
        #pragma unroll
        for (int f = 0; f < 12; ++f) {
            float w = fc1w[(j*12+f)*16 + o];
            gg += u[f]*w; gc += cv[f]*w;
        }
        g_GGc[i] = packf2(gg, gc);
    }
    if (tid < 16) {
        float e = fc1b[tid];
        for (int j = 0; j < NPG; ++j)
            #pragma unroll
            for (int f = 0; f < 12; ++f)
                e += dv[f]*fc1w[(j*12+f)*16 + tid];
        g_e1[tid] = e;
        g_sum1[tid] = 0.f; g_ss1[tid] = 0.f;
    }
    if (tid < 32) { g_sum2[tid] = 0.f; g_ss2[tid] = 0.f; }
}

// ---------------- main GCN kernel: warp-per-graph, bitmask adjacency (r7 verbatim) ----------------
__global__ void __launch_bounds__(T1, 4) gcn_kernel(const float* __restrict__ x,
                                                    const int* __restrict__ ei)
{
    __shared__ u32  sMask[WPC][NPG*2];        // 64-bit row masks
    __shared__ float sAx[WPC][NPG];           // accumulate target (x-path / degree)
    __shared__ float sAr[WPC][NPG];           // accumulate target (ones-path)
    __shared__ u64  sWxd[WPC][NPG];           // packed (x*dinv, dinv)
    __shared__ float sW2[WPC][NPG];           // sweep-2 input
    __shared__ u64  sYR[WPC][NPG];            // packed (yv, rv)
    __shared__ unsigned short sDup[WPC][EPG]; // duplicate-edge list
    __shared__ int  sNdup[WPC];
    __shared__ u64  sGGc[NPG*16];             // interleaved fc1 weights
    __shared__ float se1[16];

    int tid = threadIdx.x, w = tid >> 5, lane = tid & 31;
    for (int i = tid; i < NPG*16; i += T1) sGGc[i] = g_GGc[i];
    if (tid < 16) se1[tid] = g_e1[tid];
    __syncthreads();

    u32*  mask = sMask[w];
    float* ax  = sAx[w];
    float* ar  = sAr[w];
    u64*  wxd  = sWxd[w];
    float* w2  = sW2[w];
    u64*  yr   = sYR[w];
    unsigned short* dup = sDup[w];

    const int r1 = lane, r2 = 32 + lane;
    const bool has2 = (lane < NPG - 32);
    float psum = 0.f, pss = 0.f;
    int gbase = (blockIdx.x * WPC + w) * GPW;

    for (int gi = 0; gi < GPW; ++gi) {
        int g = gbase + gi, nb = g*NPG, eb = g*EPG;
        // P0: zero ALL 100 mask words + load x
        float x1 = x[nb + r1];
        float x2 = has2 ? x[nb + r2] : 0.f;
        mask[lane] = 0; mask[32 + lane] = 0; mask[64 + lane] = 0;
        if (lane < 2*NPG - 96) mask[96 + lane] = 0;
        if (lane == 0) sNdup[w] = 0;
        __syncwarp();
        // P1: build bitmask adjacency; atomicOr detects duplicates
        #pragma unroll 4
        for (int e = lane; e < EPG; e += 32) {
            int s = ei[eb + e] - nb;
            int d = ei[NEDGE + eb + e] - nb;
            u32 bit = 1u << (s & 31);
            u32 old = atomicOr(&mask[d*2 + (s >> 5)], bit);
            if (old & bit) {
                int k = atomicAdd(&sNdup[w], 1);
                dup[k] = (unsigned short)(d*64 + s);
            }
        }
        __syncwarp();
        int nd = sNdup[w];
        // P2: degree = 1 + popcount (+ dup events)
        {
            ax[r1] = 1.f + (float)(__popc(mask[2*r1]) + __popc(mask[2*r1+1]));
            if (has2)
                ax[r2] = 1.f + (float)(__popc(mask[2*r2]) + __popc(mask[2*r2+1]));
        }
        __syncwarp();
        for (int k = lane; k < nd; k += 32) atomicAdd(&ax[dup[k] >> 6], 1.0f);
        __syncwarp();
        float di1 = rsqrtf(ax[r1]), di2 = 0.f;
        wxd[r1] = packf2(x1*di1, di1);
        if (has2) { di2 = rsqrtf(ax[r2]); wxd[r2] = packf2(x2*di2, di2); }
        __syncwarp();
        // P3: sweep 1 (x-path and ones-path packed in f32x2)
        {
            u64 a = wxd[r1];
            u32 m0 = mask[2*r1], m1 = mask[2*r1+1];
            while (m0) { int j = __ffs(m0)-1;  m0 &= m0-1; u64 v = wxd[j]; ADD2(a, v); }
            while (m1) { int j = __ffs(m1)+31; m1 &= m1-1; u64 v = wxd[j]; ADD2(a, v); }
            ax[r1] = lo32(a); ar[r1] = hi32(a);
            if (has2) {
                u64 b = wxd[r2];
                u32 n0 = mask[2*r2], n1 = mask[2*r2+1];
                while (n0) { int j = __ffs(n0)-1;  n0 &= n0-1; u64 v = wxd[j]; ADD2(b, v); }
                while (n1) { int j = __ffs(n1)+31; n1 &= n1-1; u64 v = wxd[j]; ADD2(b, v); }
                ax[r2] = lo32(b); ar[r2] = hi32(b);
            }
        }
        __syncwarp();
        for (int k = lane; k < nd; k += 32) {
            int c = dup[k]; u64 v = wxd[c & 63];
            atomicAdd(&ax[c >> 6], lo32(v));
            atomicAdd(&ar[c >> 6], hi32(v));
        }
        __syncwarp();
        float rv1 = ar[r1]*di1, rv2 = 0.f;
        w2[r1] = ax[r1]*di1*di1;
        if (has2) { rv2 = ar[r2]*di2; w2[r2] = ax[r2]*di2*di2; }
        __syncwarp();
        // P4: sweep 2 (scalar)
        {
            float a = w2[r1];
            u32 m0 = mask[2*r1], m1 = mask[2*r1+1];
            while (m0) { int j = __ffs(m0)-1;  m0 &= m0-1; a += w2[j]; }
            while (m1) { int j = __ffs(m1)+31; m1 &= m1-1; a += w2[j]; }
            ax[r1] = a;
            if (has2) {
                float b = w2[r2];
                u32 n0 = mask[2*r2], n1 = mask[2*r2+1];
                while (n0) { int j = __ffs(n0)-1;  n0 &= n0-1; b += w2[j]; }
                while (n1) { int j = __ffs(n1)+31; n1 &= n1-1; b += w2[j]; }
                ax[r2] = b;
            }
        }
        __syncwarp();
        for (int k = lane; k < nd; k += 32) {
            int c = dup[k];
            atomicAdd(&ax[c >> 6], w2[c & 63]);
        }
        __syncwarp();
        yr[r1] = packf2(ax[r1]*di1, rv1);
        if (has2) yr[r2] = packf2(ax[r2]*di2, rv2);
        __syncwarp();
        // P5: fc1 — a1[g,o] = e1[o] + Σ_j yv[j]G[j,o] + rv[j]Gc[j,o]
        {
            int o = lane & 15, half = lane >> 4;
            int j0 = half * 25;
            u64 acc = 0;
            #pragma unroll
            for (int j = 0; j < 25; ++j) {
                u64 y = yr[j0 + j];
                u64 gg = sGGc[(j0 + j)*16 + o];
                FMA2(acc, y, gg);
            }
            float s = lo32(acc) + hi32(acc);
            s += __shfl_down_sync(0xffffffffu, s, 16);
            if (lane < 16) {
                float a = fmaxf(se1[o] + s, 0.f);
                g_a1[g*16 + o] = a;
                psum += a; pss += a*a;
            }
        }
        __syncwarp();
    }
    if (lane < 16) { atomicAdd(&g_sum1[lane], psum); atomicAdd(&g_ss1[lane], pss); }
}

// ---------------- fc2: 2 threads/graph — BN1 fold + GEMV + relu -> g_a2 + BN2 stats ----------------
__global__ void __launch_bounds__(128) fc2_kernel(const float* __restrict__ fc2w,
                                                  const float* __restrict__ fc2b,
                                                  const float* __restrict__ g1,
                                                  const float* __restrict__ bb1)
{
    __shared__ float sS[16], sOff[16];
    __shared__ float4 sW4[16*8];
    __shared__ float sc2[32];
    __shared__ float tile[4][16][33];
    __shared__ float rsum[32], rss[32];
    int tid = threadIdx.x, lane = tid & 31, w = tid >> 5;
    if (tid < 16) {
        float m = g_sum1[tid] * (1.0f/NGRAPH);
        float v = g_ss1[tid] * (1.0f/NGRAPH) - m*m;
        float sc = rsqrtf(v + BN_EPS) * g1[tid];
        sS[tid] = sc; sOff[tid] = bb1[tid] - m*sc;
    }
    if (tid < 32) { rsum[tid] = 0.f; rss[tid] = 0.f; }
    __syncthreads();
    float* sW = (float*)sW4;
    for (int i = tid; i < 512; i += 128) sW[i] = sS[i >> 5] * fc2w[i];
    if (tid < 32) {
        float c = fc2b[tid];
        #pragma unroll
        for (int r = 0; r < 16; ++r) c += sOff[r]*fc2w[r*32+tid];
        sc2[tid] = c;
    }
    __syncthreads();

    int gt = blockIdx.x*128 + tid;
    int b = gt >> 1, half = gt & 1;           // 2 threads per graph
    const float4* a4 = (const float4*)&g_a1[b*16];
    float4 r0 = a4[0], r1 = a4[1], r2 = a4[2], r3 = a4[3];
    float a[16] = {r0.x,r0.y,r0.z,r0.w, r1.x,r1.y,r1.z,r1.w,
                   r2.x,r2.y,r2.z,r2.w, r3.x,r3.y,r3.z,r3.w};
    float z[16];
    float4* out4 = (float4*)&g_a2[b*32 + half*16];
    #pragma unroll
    for (int q = 0; q < 4; ++q) {
        int o4 = half*4 + q;
        float4 acc = make_float4(sc2[o4*4], sc2[o4*4+1], sc2[o4*4+2], sc2[o4*4+3]);
        #pragma unroll
        for (int i = 0; i < 16; ++i) {
            float4 ww = sW4[i*8 + o4];
            acc.x += a[i]*ww.x; acc.y += a[i]*ww.y; acc.z += a[i]*ww.z; acc.w += a[i]*ww.w;
        }
        acc.x = fmaxf(acc.x, 0.f); acc.y = fmaxf(acc.y, 0.f);
        acc.z = fmaxf(acc.z, 0.f); acc.w = fmaxf(acc.w, 0.f);
        out4[q] = acc;
        z[q*4] = acc.x; z[q*4+1] = acc.y; z[q*4+2] = acc.z; z[q*4+3] = acc.w;
    }
    // BN2 stats: warp covers 16 graphs × 32 cols; tile[graph-in-warp][col]
    {
        float* trow = &tile[w][lane >> 1][(lane & 1)*16];
        #pragma unroll
        for (int i = 0; i < 16; ++i) trow[i] = z[i];
    }
    __syncwarp();
    float s = 0.f, ss = 0.f;
    #pragma unroll
    for (int j = 0; j < 16; ++j) {
        float v = tile[w][j][lane];
        s += v; ss += v*v;
    }
    atomicAdd(&rsum[lane], s);
    atomicAdd(&rss[lane], ss);
    __syncthreads();
    if (tid < 32) { atomicAdd(&g_sum2[tid], rsum[tid]); atomicAdd(&g_ss2[tid], rss[tid]); }
}

// ---------------- fc3: 2 threads/graph — BN2 fold + final logits ----------------
__global__ void __launch_bounds__(128) fc3_kernel(float* __restrict__ out,
                                                  const float* __restrict__ fc3w,
                                                  const float* __restrict__ fc3b,
                                                  const float* __restrict__ g2,
                                                  const float* __restrict__ bb2)
{
    __shared__ float sS[32], sOff[32], sW[64], sc3[2];
    int tid = threadIdx.x;
    if (tid < 32) {
        float m = g_sum2[tid] * (1.0f/NGRAPH);
        float v = g_ss2[tid] * (1.0f/NGRAPH) - m*m;
        float sc = rsqrtf(v + BN_EPS) * g2[tid];
        sS[tid] = sc; sOff[tid] = bb2[tid] - m*sc;
    }
    __syncthreads();
    if (tid < 64) sW[tid] = sS[tid >> 1] * fc3w[tid];
    if (tid < 2) {
        float c = fc3b[tid];
        #pragma unroll
        for (int r = 0; r < 32; ++r) c += sOff[r]*fc3w[r*2+tid];
        sc3[tid] = c;
    }
    __syncthreads();
    int gt = blockIdx.x*128 + tid;
    int b = gt >> 1, half = gt & 1;
    const float4* a2r = (const float4*)&g_a2[b*32 + half*16];
    float o0 = half ? 0.f : sc3[0];
    float o1 = half ? 0.f : sc3[1];
    #pragma unroll
    for (int q = 0; q < 4; ++q) {
        float4 v = a2r[q];
        int c0 = half*16 + q*4;
        o0 += v.x*sW[(c0+0)*2]   + v.y*sW[(c0+1)*2]   + v.z*sW[(c0+2)*2]   + v.w*sW[(c0+3)*2];
        o1 += v.x*sW[(c0+0)*2+1] + v.y*sW[(c0+1)*2+1] + v.z*sW[(c0+2)*2+1] + v.w*sW[(c0+3)*2+1];
    }
    o0 += __shfl_down_sync(0xffffffffu, o0, 1);
    o1 += __shfl_down_sync(0xffffffffu, o1, 1);
    if (half == 0) ((float2*)out)[b] = make_float2(o0, o1);
}

// ---------------- launch ----------------
extern "C" void kernel_launch(void* const* d_in, const int* in_sizes, int n_in,
                              void* d_out, int out_size)
{
    const float* x    = (const float*)d_in[0];
    const int*   ei   = (const int*)  d_in[1];
    const float* W11  = (const float*)d_in[2];
    const float* b11  = (const float*)d_in[3];
    const float* W21  = (const float*)d_in[4];
    const float* b21  = (const float*)d_in[5];
    const float* W12  = (const float*)d_in[6];
    const float* b12  = (const float*)d_in[7];
    const float* W22  = (const float*)d_in[8];
    const float* b22  = (const float*)d_in[9];
    const float* W13  = (const float*)d_in[10];
    const float* b13  = (const float*)d_in[11];
    const float* W23  = (const float*)d_in[12];
    const float* b23  = (const float*)d_in[13];
    const float* fc1w = (const float*)d_in[14];
    const float* fc1b = (const float*)d_in[15];
    const float* bn1g = (const float*)d_in[16];
    const float* bn1b = (const float*)d_in[17];
    const float* fc2w = (const float*)d_in[18];
    const float* fc2b = (const float*)d_in[19];
    const float* bn2g = (const float*)d_in[20];
    const float* bn2b = (const float*)d_in[21];
    const float* fc3w = (const float*)d_in[22];
    const float* fc3b = (const float*)d_in[23];

    prep_kernel<<<1, 256>>>(W11,b11,W21,b21,W12,b12,W22,b22,W13,b13,W23,b23,fc1w,fc1b);
    gcn_kernel<<<NGRAPH/(WPC*GPW), T1>>>(x, ei);
    fc2_kernel<<<NGRAPH*2/128, 128>>>(fc2w, fc2b, bn1g, bn1b);
    fc3_kernel<<<NGRAPH*2/128, 128>>>((float*)d_out, fc3w, fc3b, bn2g, bn2b);
}